// round 10
// baseline (speedup 1.0000x reference)
#include <cuda_runtime.h>
#include <cuda_fp16.h>
#include <math.h>

#define T_LEN 512
#define BATCH 64
#define HID   512
#define BH    (BATCH * HID)
#define WPH   520              // op0 weight pitch (halves): u32-pitch 260 ≡ 4 mod 32
#define BPH   40               // stage pitch (halves): u32-pitch 20 -> conflict-free
#define BUFH  (64 * BPH)       // 2560 halves per chunk buffer (5120 B)
#define NBUF  3                // staging depth per warp
#define PPITCH 33              // partials pitch (floats)

// ---------------------------------------------------------------------------
// Static device scratch
// ---------------------------------------------------------------------------
__device__ __align__(16) __half g_xr[(size_t)BATCH * T_LEN * HID];  // fp16 x
__device__ __align__(16) __half g_hseq[(size_t)T_LEN * BH];         // L0 hidden seq (fp16)
__device__ __align__(16) __half g_h2[2 * BH];                       // L1 hidden dbuf (fp16)
__device__ unsigned g_cnt[2 * T_LEN * 8];                           // per-(layer,step,group)

// ---------------------------------------------------------------------------
// Helpers
// ---------------------------------------------------------------------------
__device__ __forceinline__ unsigned pack2(float lo, float hi) {
    __half2 h = __floats2half2_rn(lo, hi);
    return *reinterpret_cast<unsigned*>(&h);
}

__device__ __forceinline__ void mma_m16n8k16(float c[4], const unsigned a[4], const unsigned b[2]) {
    asm volatile(
        "mma.sync.aligned.m16n8k16.row.col.f32.f16.f16.f32 "
        "{%0,%1,%2,%3}, {%4,%5,%6,%7}, {%8,%9}, {%0,%1,%2,%3};"
        : "+f"(c[0]), "+f"(c[1]), "+f"(c[2]), "+f"(c[3])
        : "r"(a[0]), "r"(a[1]), "r"(a[2]), "r"(a[3]), "r"(b[0]), "r"(b[1]));
}

// Gate-interleaved column n = 4*j + gate -> original weight row r = gate*512 + j
__device__ __forceinline__ int remap_row(int n) { return ((n & 3) << 9) | (n >> 2); }

__device__ __forceinline__ void cp_commit() {
    asm volatile("cp.async.commit_group;" ::: "memory");
}
__device__ __forceinline__ void cp_wait0() { asm volatile("cp.async.wait_group 0;" ::: "memory"); }
__device__ __forceinline__ void cp_wait1() { asm volatile("cp.async.wait_group 1;" ::: "memory"); }
__device__ __forceinline__ void cp_wait2() { asm volatile("cp.async.wait_group 2;" ::: "memory"); }

// Sentinel wait: warp 0 polls the 8 group counters for one (layer,step)
// (lanes 0-7, one coalesced 32B L2 request per iteration), then publishes
// `target` to an SMEM word with release; warps 1-7 acquire-spin on SMEM.
// Chain: producer red.release.gpu -> ld.acquire.gpu -> st.release.cta ->
// ld.acquire.cta => consumer's subsequent cp.async sees the h data.
__device__ __forceinline__ void sentinel_wait(unsigned* gbase, unsigned* sflag,
                                              unsigned target, int w, int lane) {
    unsigned sa = (unsigned)__cvta_generic_to_shared(sflag);
    if (w == 0) {
        for (;;) {
            unsigned v = 8u;
            if (lane < 8)
                asm volatile("ld.acquire.gpu.global.u32 %0, [%1];"
                             : "=r"(v) : "l"(gbase + lane));
            if (__all_sync(0xffffffffu, v >= 8u)) break;
        }
        if (lane == 0)
            asm volatile("st.release.cta.shared.u32 [%0], %1;"
                         :: "r"(sa), "r"(target) : "memory");
        __syncwarp();
    } else {
        unsigned v;
        do {
            asm volatile("ld.acquire.cta.shared.u32 %0, [%1];" : "=r"(v) : "r"(sa));
        } while ((int)(v - target) < 0);
    }
}

// Issue one warp-private 64x16(half) chunk = 64 rows x 32 B via cp.async.cg.
__device__ __forceinline__ void issue_chunk(__half* buf, const __half* __restrict__ src,
                                            size_t stride, int col0, int lane) {
#pragma unroll
    for (int i = 0; i < 4; i++) {
        int cc = lane + (i << 5);
        int row = cc >> 1, h8 = (cc & 1) << 3;
        const __half* g = src + (size_t)row * stride + col0 + h8;
        unsigned s = (unsigned)__cvta_generic_to_shared(buf + row * BPH + h8);
        asm volatile("cp.async.cg.shared.global [%0], [%1], 16;" :: "r"(s), "l"(g));
    }
}

// Load A-frags for one k16 chunk (m64 rows), fp16: 4 mt x 4 .b32 regs.
__device__ __forceinline__ void load_afr(unsigned afr[4][4], const __half* buf,
                                         int gi, int ti) {
    const unsigned* a32 = (const unsigned*)buf;   // u32 pitch = BPH/2 = 20
#pragma unroll
    for (int mt = 0; mt < 4; mt++) {
        int r = mt * 16;
        afr[mt][0] = a32[(r + gi) * 20 + ti];
        afr[mt][1] = a32[(r + gi + 8) * 20 + ti];
        afr[mt][2] = a32[(r + gi) * 20 + ti + 4];
        afr[mt][3] = a32[(r + gi + 8) * 20 + ti + 4];
    }
}

// MMA over one k16 chunk with B from SMEM (op0 path).
__device__ __forceinline__ void mma_chunk_smemB(float acc[4][4][4], const __half* buf,
                                                const __half* sW0, int kbase,
                                                int gi, int ti) {
    unsigned afr[4][4];
    load_afr(afr, buf, gi, ti);
    const unsigned* w32 = (const unsigned*)sW0;   // u32 pitch = WPH/2 = 260
    int kb = (kbase >> 1) + ti;
#pragma unroll
    for (int nt = 0; nt < 4; nt++) {
        unsigned bfr[2];
        bfr[0] = w32[(nt * 8 + gi) * 260 + kb];
        bfr[1] = w32[(nt * 8 + gi) * 260 + kb + 4];
#pragma unroll
        for (int mt = 0; mt < 4; mt++) mma_m16n8k16(acc[mt][nt], afr[mt], bfr);
    }
}

// MMA over one k16 chunk with B from registers (op1 / critical path).
__device__ __forceinline__ void mma_chunk_regB(float acc[4][4][4], const __half* buf,
                                               const unsigned breg[4][4][2], int u,
                                               int gi, int ti) {
    unsigned afr[4][4];
    load_afr(afr, buf, gi, ti);
#pragma unroll
    for (int nt = 0; nt < 4; nt++)
#pragma unroll
        for (int mt = 0; mt < 4; mt++)
            mma_m16n8k16(acc[mt][nt], afr[mt], breg[nt][u]);
}

__device__ __forceinline__ float fsig(float x) {
    return __fdividef(1.f, 1.f + __expf(-x));
}
__device__ __forceinline__ float ftanh(float x) {
    return 1.f - __fdividef(2.f, __expf(2.f * x) + 1.f);
}

// ---------------------------------------------------------------------------
// Fused dual-layer persistent LSTM (fp16 operands, fp32 accumulate).
// 128 blocks (64/layer), 256 threads (8 warps). Block owns 32 interleaved
// gate cols. Warp w owns K-slice [64w,64w+64) per operand, staged as 4 k16
// chunks through a depth-3 private cp.async pipeline. op1 weights in regs.
// Sentinel-warp dependency waits (warp 0 polls L2; others spin on SMEM).
// ---------------------------------------------------------------------------
extern "C" __global__ void __launch_bounds__(256, 1)
lstm_fused(const float* __restrict__ Wx0, const float* __restrict__ bx0,
           const float* __restrict__ Wh0, const float* __restrict__ bh0,
           const float* __restrict__ Wx1, const float* __restrict__ bx1,
           const float* __restrict__ Wh1, const float* __restrict__ bh1,
           float* __restrict__ out) {
    extern __shared__ __half smem[];
    __half* sW0 = smem;                               // 32*WPH = 16640 halves
    __half* sStage = smem + 32 * WPH;                 // 8*NBUF*BUFH = 61440 halves
    float* sC = (float*)(sStage + 8 * NBUF * BUFH);   // 512 floats
    float* sBias = sC + 512;                          // 32 floats
    float* sP = (float*)sStage;                       // partials alias (67584B <= 122880B)
    __shared__ unsigned sGo[2];                       // sentinel broadcast words

    const int tid = threadIdx.x;
    const int w = tid >> 5;
    const int lane = tid & 31;
    const int gi = lane >> 2;
    const int ti = lane & 3;
    const int layer = blockIdx.x >> 6;
    const int bslot = blockIdx.x & 63;
    const int n_blk = bslot * 32;
    const int kw = w * 64;                            // warp K-slice base (halves)

    __half* bufs[NBUF];
#pragma unroll
    for (int i = 0; i < NBUF; i++) bufs[i] = sStage + (w * NBUF + i) * BUFH;

    // op0 weight matrix -> SMEM ; op1 weight matrix -> registers
    const float* W0 = layer ? Wh1 : Wx0;   // op0: L0=x·Wx0, L1=h2·Wh1
    const float* W1 = layer ? Wx1 : Wh0;   // op1: L0=h1·Wh0, L1=h1·Wx1
    const float* bxp = layer ? bx1 : bx0;
    const float* bhp = layer ? bh1 : bh0;

    if (tid < 2) sGo[tid] = 0u;

    // Stage op0 weights once (remapped rows, fp16)
    for (int v = tid; v < 32 * 128; v += 256) {
        int row = v >> 7, c4 = (v & 127) * 4;
        int r = remap_row(n_blk + row);
        float4 f = *(const float4*)(W0 + (size_t)r * 512 + c4);
        __half2* d = (__half2*)(sW0 + (size_t)row * WPH + c4);
        d[0] = __floats2half2_rn(f.x, f.y);
        d[1] = __floats2half2_rn(f.z, f.w);
    }
    if (tid < 32) {
        int r = remap_row(n_blk + tid);
        sBias[tid] = bxp[r] + bhp[r];
    }
    for (int v = tid; v < 512; v += 256) sC[v] = 0.f;

    // Preload op1 B-fragments (fp16, 32 regs; constant across steps)
    unsigned breg[4][4][2];
#pragma unroll
    for (int nt = 0; nt < 4; nt++) {
        int r = remap_row(n_blk + nt * 8 + gi);
        const float* wr = W1 + (size_t)r * 512 + kw;
#pragma unroll
        for (int u = 0; u < 4; u++) {
            breg[nt][u][0] = pack2(wr[16 * u + 2 * ti], wr[16 * u + 2 * ti + 1]);
            breg[nt][u][1] = pack2(wr[16 * u + 2 * ti + 8], wr[16 * u + 2 * ti + 9]);
        }
    }
    __syncthreads();

    for (int t = 0; t < T_LEN; t++) {
        float acc[4][4][4];
#pragma unroll
        for (int a = 0; a < 4; a++)
#pragma unroll
            for (int b = 0; b < 4; b++)
#pragma unroll
                for (int c = 0; c < 4; c++) acc[a][b][c] = 0.f;

        const __half* srcs[2];
        size_t strds[2];
        bool vals[2];
        if (layer == 0) {
            srcs[0] = g_xr + (size_t)t * 512;            // x[b][t][:]
            strds[0] = (size_t)T_LEN * HID;  vals[0] = true;
            srcs[1] = g_hseq + (size_t)(t - 1) * BH;
            strds[1] = HID;                  vals[1] = (t > 0);
        } else {
            srcs[0] = g_h2 + (size_t)((t + 1) & 1) * BH;
            strds[0] = HID;                  vals[0] = (t > 0);
            srcs[1] = g_hseq + (size_t)t * BH;
            strds[1] = HID;                  vals[1] = true;
        }

        // op0 dependency (layer 1: own cohort, previous step) — sentinel wait
        if (layer == 1 && t > 0)
            sentinel_wait(&g_cnt[(T_LEN + (t - 1)) * 8], &sGo[0], (unsigned)t, w, lane);

        // Pre-issue op0 chunks 0..2 (always commit to keep group counts aligned)
#pragma unroll
        for (int c = 0; c < 3; c++) {
            if (vals[0]) issue_chunk(bufs[c], srcs[0], strds[0], kw + 16 * c, lane);
            cp_commit();
        }

#pragma unroll
        for (int g = 0; g < 8; g++) {
            if (g < 6) cp_wait2(); else if (g == 6) cp_wait1(); else cp_wait0();
            const int op = g >> 2;
            if (vals[op]) {
                if (op == 0)
                    mma_chunk_smemB(acc, bufs[g % NBUF], sW0, kw + 16 * (g & 3), gi, ti);
                else
                    mma_chunk_regB(acc, bufs[g % NBUF], breg, g & 3, gi, ti);
            }
            const int gn = g + 3;
            if (gn < 8) {
                if (gn == 4) {   // op1 dependency (h1) — sentinel wait
                    if (layer == 0) {
                        if (t > 0)
                            sentinel_wait(&g_cnt[(t - 1) * 8], &sGo[1], (unsigned)t, w, lane);
                    } else {
                        sentinel_wait(&g_cnt[t * 8], &sGo[1], (unsigned)(t + 1), w, lane);
                    }
                }
                const int opn = gn >> 2;
                if (vals[opn])
                    issue_chunk(bufs[gn % NBUF], srcs[opn], strds[opn],
                                kw + 16 * (gn & 3), lane);
                cp_commit();
            }
        }

        __syncthreads();   // all warps done with stage bufs before partials alias

        // Write K-split partials
#pragma unroll
        for (int mt = 0; mt < 4; mt++) {
#pragma unroll
            for (int nt = 0; nt < 4; nt++) {
                int m = mt * 16 + gi;
                int n = nt * 8 + 2 * ti;
                int base = (w * 64 + m) * PPITCH + n;
                sP[base]     = acc[mt][nt][0];
                sP[base + 1] = acc[mt][nt][1];
                sP[base + 8 * PPITCH]     = acc[mt][nt][2];
                sP[base + 8 * PPITCH + 1] = acc[mt][nt][3];
            }
        }
        __syncthreads();

        // Reduce partials + bias + gate math + state update
        __half* h_out_h;
        if (layer == 0)
            h_out_h = g_hseq + (size_t)t * BH;
        else
            h_out_h = g_h2 + (size_t)(t & 1) * BH;
        const bool final_raw = (layer == 1) && (t == T_LEN - 1);

#pragma unroll
        for (int qq = 0; qq < 2; qq++) {
            int q = tid + (qq << 8);
            int b = q >> 3, j = q & 7;
            float s0 = 0.f, s1 = 0.f, s2 = 0.f, s3 = 0.f;
#pragma unroll
            for (int pw = 0; pw < 8; pw++) {
                int rb = (pw * 64 + b) * PPITCH + j * 4;
                s0 += sP[rb];
                s1 += sP[rb + 1];
                s2 += sP[rb + 2];
                s3 += sP[rb + 3];
            }
            float fg = fsig(s0 + sBias[j * 4 + 0]);
            float ig = fsig(s1 + sBias[j * 4 + 1]);
            float gg = ftanh(s2 + sBias[j * 4 + 2]);
            float og = fsig(s3 + sBias[j * 4 + 3]);
            float c = sC[b * 8 + j];
            c = fg * c + ig * gg;
            sC[b * 8 + j] = c;
            float hv = og * ftanh(c);
            int col = (n_blk >> 2) + j;
            if (final_raw) out[(size_t)b * HID + col] = hv;
            else           h_out_h[(size_t)b * HID + col] = __float2half_rn(hv);
        }

        // Publish: block-sync then ONE release-reduction
        __syncthreads();
        if (tid == 0) {
            unsigned* p = &g_cnt[((layer * T_LEN) + t) * 8 + (bslot >> 3)];
            asm volatile("red.release.gpu.global.add.u32 [%0], %1;"
                         :: "l"(p), "r"(1u) : "memory");
        }
    }
}

// ---------------------------------------------------------------------------
// Prep: fp16-convert x AND reset counters (2 graph nodes total)
// ---------------------------------------------------------------------------
__global__ void prep(const float4* __restrict__ x) {
    size_t i = (size_t)blockIdx.x * blockDim.x + threadIdx.x;
    if (i < 2 * T_LEN * 8) g_cnt[i] = 0;
    float4 v = x[i];
    __half2* dst = (__half2*)g_xr;
    dst[i * 2]     = __floats2half2_rn(v.x, v.y);
    dst[i * 2 + 1] = __floats2half2_rn(v.z, v.w);
}

// ---------------------------------------------------------------------------
// Launch: 2 graph nodes
// ---------------------------------------------------------------------------
extern "C" void kernel_launch(void* const* d_in, const int* in_sizes, int n_in,
                              void* d_out, int out_size) {
    const float* x   = (const float*)d_in[0];
    const float* Wx0 = (const float*)d_in[1];
    const float* bx0 = (const float*)d_in[2];
    const float* Wh0 = (const float*)d_in[3];
    const float* bh0 = (const float*)d_in[4];
    const float* Wx1 = (const float*)d_in[5];
    const float* bx1 = (const float*)d_in[6];
    const float* Wh1 = (const float*)d_in[7];
    const float* bh1 = (const float*)d_in[8];

    const size_t SMEM_BYTES =
        (size_t)(32 * WPH + 8 * NBUF * BUFH) * sizeof(__half)
        + (512 + 32) * sizeof(float);
    cudaFuncSetAttribute(lstm_fused, cudaFuncAttributeMaxDynamicSharedMemorySize,
                         (int)SMEM_BYTES);

    prep<<<4096, 1024>>>((const float4*)x);
    lstm_fused<<<128, 256, SMEM_BYTES>>>(Wx0, bx0, Wh0, bh0,
                                         Wx1, bx1, Wh1, bh1, (float*)d_out);
}